// round 14
// baseline (speedup 1.0000x reference)
#include <cuda_runtime.h>

// Problem constants
#define NB 8
#define NC 21
#define NW 512
#define NH 512
#define KK 5
#define KPAD 2
#define PLANE (NW * NH)

// 5-lane packing constants (6-bit lanes at bits 0,6,12,18,24; labels < 32)
#define LREP 0x01041041u   // 1 in each lane
#define CADD 0x1F7DF7DFu   // 31 in each lane
#define MBIT 0x20820820u   // bit5 of each lane

// Block: 256 threads, one row w, 2 contiguous h-pixels per thread (float2).
// Channel loop unroll 10 -> 10 in-flight LDG.64 per warp (~36 regs,
// 7 blocks/SM = 87.5% nominal occupancy; MLP x occupancy product +38%).
// Grid: (NW, NB).
__global__ __launch_bounds__(256)
void weight_matrix_kernel(const float* __restrict__ x,
                          const int*   __restrict__ y,
                          float*       __restrict__ out)
{
    // spack[i] = labels of rows w-2..w+2 at global col (i-2), packed into
    // 6-bit lanes (row r -> bits 6r). Cols outside [0,512) pack to 0 (Unfold
    // zero padding; lane 0 mismatches any class c!=0, matching ref).
    __shared__ unsigned int spack[520];   // 2080 B

    const int w   = blockIdx.x;
    const int b   = blockIdx.y;
    const int tid = threadIdx.x;
    const int h0  = tid * 2;

    // ---- phase 1: stage packed column words (completes under the stream) ----
    const int* yb = y + b * PLANE;
    if (w >= KPAD && w < NW - KK + KPAD + 1) {
        // interior rows (508/512): no per-row bounds checks
        const int* yr = yb + (w - KPAD) * NH;
        #pragma unroll
        for (int k = 0; k < 3; k++) {                  // 3*256 = 768 >= 520
            const int i = tid + k * 256;
            if (i < 520) {
                const int gc = i - KPAD;
                unsigned int pack = 0;
                if ((unsigned)gc < NH) {
                    pack  = (unsigned)__ldg(yr + gc);
                    pack |= (unsigned)__ldg(yr + NH     + gc) << 6;
                    pack |= (unsigned)__ldg(yr + 2 * NH + gc) << 12;
                    pack |= (unsigned)__ldg(yr + 3 * NH + gc) << 18;
                    pack |= (unsigned)__ldg(yr + 4 * NH + gc) << 24;
                }
                spack[i] = pack;
            }
        }
    } else {
        // boundary rows: full predication
        #pragma unroll
        for (int k = 0; k < 3; k++) {
            const int i = tid + k * 256;
            if (i < 520) {
                const int gc = i - KPAD;
                unsigned int pack = 0;
                if ((unsigned)gc < NH) {
                    #pragma unroll
                    for (int r = 0; r < KK; r++) {
                        const int gr = w - KPAD + r;
                        unsigned int v = 0;
                        if ((unsigned)gr < NW) v = (unsigned)__ldg(&yb[gr * NH + gc]);
                        pack |= v << (6 * r);
                    }
                }
                spack[i] = pack;
            }
        }
    }

    // ---- phase 2: argmax over 21 channels (float2; strict > => first idx).
    //      __ldcs: evict-first, x is single-use — keep L2 for y/out. ----
    const float* xb = x + (size_t)(b * NC) * PLANE + w * NH + h0;
    float2 best = __ldcs(reinterpret_cast<const float2*>(xb));
    int bc0 = 0, bc1 = 0;

    #pragma unroll 10
    for (int c = 1; c < NC; c++) {
        const float2 v = __ldcs(reinterpret_cast<const float2*>(xb + c * PLANE));
        if (v.x > best.x) { best.x = v.x; bc0 = c; }
        if (v.y > best.y) { best.y = v.y; bc1 = c; }
    }

    // ---- barrier for spack (staging long since complete) ----
    __syncthreads();

    // ---- phase 3: 5x5 mismatch count via packed lanes ----
    // Pixel p (p=0,1) needs stored cols h0+p .. h0+p+4 -> words h0..h0+5.
    // h0 even -> &spack[h0] is 8B aligned: three LDS.64.
    const uint2 l0 = *reinterpret_cast<const uint2*>(&spack[h0]);
    const uint2 l1 = *reinterpret_cast<const uint2*>(&spack[h0 + 2]);
    const uint2 l2 = *reinterpret_cast<const uint2*>(&spack[h0 + 4]);
    const unsigned int w0 = l0.x, w1 = l0.y, w2 = l1.x;
    const unsigned int w3 = l1.y, w4 = l2.x, w5 = l2.y;

    const unsigned int r0 = (unsigned)bc0 * LREP;
    const unsigned int r1 = (unsigned)bc1 * LREP;

    // popc(((word ^ rep) + CADD) & MBIT) = # mismatching rows in that column
    #define CNT(wd, rp) __popc((((wd) ^ (rp)) + CADD) & MBIT)
    const int cnt0 = CNT(w0,r0)+CNT(w1,r0)+CNT(w2,r0)+CNT(w3,r0)+CNT(w4,r0);
    const int cnt1 = CNT(w1,r1)+CNT(w2,r1)+CNT(w3,r1)+CNT(w4,r1)+CNT(w5,r1);
    #undef CNT

    float2 o;
    o.x = 1.0f + 1.5f * (float)cnt0;
    o.y = 1.0f + 1.5f * (float)cnt1;

    // streaming store: out is write-once, keep L2 for y reuse
    __stcs(reinterpret_cast<float2*>(out + (b * NW + w) * NH + h0), o);
}

extern "C" void kernel_launch(void* const* d_in, const int* in_sizes, int n_in,
                              void* d_out, int out_size)
{
    const float* x = (const float*)d_in[0];
    const int*   y = (const int*)d_in[1];
    float*       o = (float*)d_out;

    dim3 grid(NW, NB);
    weight_matrix_kernel<<<grid, 256>>>(x, y, o);
}

// round 15
// speedup vs baseline: 1.0935x; 1.0935x over previous
#include <cuda_runtime.h>

// Problem constants
#define NB 8
#define NC 21
#define NW 512
#define NH 512
#define KK 5
#define KPAD 2
#define PLANE (NW * NH)

// 5-lane packing constants (6-bit lanes at bits 0,6,12,18,24; labels < 32)
#define LREP 0x01041041u   // 1 in each lane
#define CADD 0x1F7DF7DFu   // 31 in each lane
#define MBIT 0x20820820u   // bit5 of each lane

// Block: 256 threads, one row w, 2 contiguous h-pixels per thread (float2).
// ~30 regs -> 8 blocks/SM = 2048 threads = full nominal occupancy.
// Channel loop unroll 7 (compiler sweet spot at the 32-reg budget).
// Grid: (NW, NB).
__global__ __launch_bounds__(256)
void weight_matrix_kernel(const float* __restrict__ x,
                          const int*   __restrict__ y,
                          float*       __restrict__ out)
{
    // spack[i] = labels of rows w-2..w+2 at global col (i-2), packed into
    // 6-bit lanes (row r -> bits 6r). Cols outside [0,512) pack to 0 (Unfold
    // zero padding; lane 0 mismatches any class c!=0, matching ref).
    __shared__ unsigned int spack[520];   // 2080 B

    const int w   = blockIdx.x;
    const int b   = blockIdx.y;
    const int tid = threadIdx.x;
    const int h0  = tid * 2;

    // ---- phase 1: stage packed column words (completes under the stream) ----
    const int* yb = y + b * PLANE;
    if (w >= KPAD && w < NW - KK + KPAD + 1) {
        // interior rows (508/512): no per-row bounds checks
        const int* yr = yb + (w - KPAD) * NH;
        #pragma unroll
        for (int k = 0; k < 3; k++) {                  // 3*256 = 768 >= 520
            const int i = tid + k * 256;
            if (i < 520) {
                const int gc = i - KPAD;
                unsigned int pack = 0;
                if ((unsigned)gc < NH) {
                    pack  = (unsigned)__ldg(yr + gc);
                    pack |= (unsigned)__ldg(yr + NH     + gc) << 6;
                    pack |= (unsigned)__ldg(yr + 2 * NH + gc) << 12;
                    pack |= (unsigned)__ldg(yr + 3 * NH + gc) << 18;
                    pack |= (unsigned)__ldg(yr + 4 * NH + gc) << 24;
                }
                spack[i] = pack;
            }
        }
    } else {
        // boundary rows: full predication
        #pragma unroll
        for (int k = 0; k < 3; k++) {
            const int i = tid + k * 256;
            if (i < 520) {
                const int gc = i - KPAD;
                unsigned int pack = 0;
                if ((unsigned)gc < NH) {
                    #pragma unroll
                    for (int r = 0; r < KK; r++) {
                        const int gr = w - KPAD + r;
                        unsigned int v = 0;
                        if ((unsigned)gr < NW) v = (unsigned)__ldg(&yb[gr * NH + gc]);
                        pack |= v << (6 * r);
                    }
                }
                spack[i] = pack;
            }
        }
    }

    // ---- phase 2: argmax over 21 channels (float2; strict > => first idx).
    //      __ldcs: evict-first, x is single-use — keep L2 for y/out. ----
    const float* xb = x + (size_t)(b * NC) * PLANE + w * NH + h0;
    float2 best = __ldcs(reinterpret_cast<const float2*>(xb));
    int bc0 = 0, bc1 = 0;

    #pragma unroll 7
    for (int c = 1; c < NC; c++) {
        const float2 v = __ldcs(reinterpret_cast<const float2*>(xb + c * PLANE));
        if (v.x > best.x) { best.x = v.x; bc0 = c; }
        if (v.y > best.y) { best.y = v.y; bc1 = c; }
    }

    // ---- barrier for spack (staging long since complete) ----
    __syncthreads();

    // ---- phase 3: 5x5 mismatch count via packed lanes ----
    // Pixel p (p=0,1) needs stored cols h0+p .. h0+p+4 -> words h0..h0+5.
    // h0 even -> &spack[h0] is 8B aligned: three LDS.64.
    const uint2 l0 = *reinterpret_cast<const uint2*>(&spack[h0]);
    const uint2 l1 = *reinterpret_cast<const uint2*>(&spack[h0 + 2]);
    const uint2 l2 = *reinterpret_cast<const uint2*>(&spack[h0 + 4]);
    const unsigned int w0 = l0.x, w1 = l0.y, w2 = l1.x;
    const unsigned int w3 = l1.y, w4 = l2.x, w5 = l2.y;

    const unsigned int r0 = (unsigned)bc0 * LREP;
    const unsigned int r1 = (unsigned)bc1 * LREP;

    // popc(((word ^ rep) + CADD) & MBIT) = # mismatching rows in that column
    #define CNT(wd, rp) __popc((((wd) ^ (rp)) + CADD) & MBIT)
    const int cnt0 = CNT(w0,r0)+CNT(w1,r0)+CNT(w2,r0)+CNT(w3,r0)+CNT(w4,r0);
    const int cnt1 = CNT(w1,r1)+CNT(w2,r1)+CNT(w3,r1)+CNT(w4,r1)+CNT(w5,r1);
    #undef CNT

    float2 o;
    o.x = 1.0f + 1.5f * (float)cnt0;
    o.y = 1.0f + 1.5f * (float)cnt1;

    // streaming store: out is write-once, keep L2 for y reuse
    __stcs(reinterpret_cast<float2*>(out + (b * NW + w) * NH + h0), o);
}

extern "C" void kernel_launch(void* const* d_in, const int* in_sizes, int n_in,
                              void* d_out, int out_size)
{
    const float* x = (const float*)d_in[0];
    const int*   y = (const int*)d_in[1];
    float*       o = (float*)d_out;

    dim3 grid(NW, NB);
    weight_matrix_kernel<<<grid, 256>>>(x, y, o);
}

// round 16
// speedup vs baseline: 1.1031x; 1.0088x over previous
#include <cuda_runtime.h>

// Problem constants
#define NB 8
#define NC 21
#define NW 512
#define NH 512
#define KK 5
#define KPAD 2
#define PLANE (NW * NH)

// 5-lane packing constants (6-bit lanes at bits 0,6,12,18,24; labels < 32)
#define LREP 0x01041041u   // 1 in each lane
#define CADD 0x1F7DF7DFu   // 31 in each lane
#define MBIT 0x20820820u   // bit5 of each lane

// Block: 256 threads, one row w, 2 contiguous h-pixels per thread (float2).
// ~30 regs -> 8 blocks/SM = 2048 threads = full nominal occupancy.
// Channel loop unroll 7 (compiler sweet spot at the 32-reg budget).
// Grid: (NW, NB).
__global__ __launch_bounds__(256)
void weight_matrix_kernel(const float* __restrict__ x,
                          const int*   __restrict__ y,
                          float*       __restrict__ out)
{
    // spack[i] = labels of rows w-2..w+2 at global col (i-2), packed into
    // 6-bit lanes (row r -> bits 6r). Cols outside [0,512) pack to 0 (Unfold
    // zero padding; lane 0 mismatches any class c!=0, matching ref).
    __shared__ unsigned int spack[520];   // 2080 B

    const int w   = blockIdx.x;
    const int b   = blockIdx.y;
    const int tid = threadIdx.x;
    const int h0  = tid * 2;

    // ---- phase 1: stage packed column words (completes under the stream) ----
    const int* yb = y + b * PLANE;
    if (w >= KPAD && w < NW - KK + KPAD + 1) {
        // interior rows (508/512): no per-row bounds checks
        const int* yr = yb + (w - KPAD) * NH;
        #pragma unroll
        for (int k = 0; k < 3; k++) {                  // 3*256 = 768 >= 520
            const int i = tid + k * 256;
            if (i < 520) {
                const int gc = i - KPAD;
                unsigned int pack = 0;
                if ((unsigned)gc < NH) {
                    pack  = (unsigned)__ldg(yr + gc);
                    pack |= (unsigned)__ldg(yr + NH     + gc) << 6;
                    pack |= (unsigned)__ldg(yr + 2 * NH + gc) << 12;
                    pack |= (unsigned)__ldg(yr + 3 * NH + gc) << 18;
                    pack |= (unsigned)__ldg(yr + 4 * NH + gc) << 24;
                }
                spack[i] = pack;
            }
        }
    } else {
        // boundary rows: full predication
        #pragma unroll
        for (int k = 0; k < 3; k++) {
            const int i = tid + k * 256;
            if (i < 520) {
                const int gc = i - KPAD;
                unsigned int pack = 0;
                if ((unsigned)gc < NH) {
                    #pragma unroll
                    for (int r = 0; r < KK; r++) {
                        const int gr = w - KPAD + r;
                        unsigned int v = 0;
                        if ((unsigned)gr < NW) v = (unsigned)__ldg(&yb[gr * NH + gc]);
                        pack |= v << (6 * r);
                    }
                }
                spack[i] = pack;
            }
        }
    }

    // ---- phase 2: argmax over 21 channels (float2; strict > => first idx).
    //      __ldcs: evict-first, x is single-use — keep L2 for y reuse. ----
    const float* xb = x + (size_t)(b * NC) * PLANE + w * NH + h0;
    float2 best = __ldcs(reinterpret_cast<const float2*>(xb));
    int bc0 = 0, bc1 = 0;

    #pragma unroll 7
    for (int c = 1; c < NC; c++) {
        const float2 v = __ldcs(reinterpret_cast<const float2*>(xb + c * PLANE));
        if (v.x > best.x) { best.x = v.x; bc0 = c; }
        if (v.y > best.y) { best.y = v.y; bc1 = c; }
    }

    // ---- barrier for spack (staging long since complete) ----
    __syncthreads();

    // ---- phase 3: 5x5 mismatch count via packed lanes ----
    // Pixel p (p=0,1) needs stored cols h0+p .. h0+p+4 -> words h0..h0+5.
    // h0 even -> &spack[h0] is 8B aligned: three LDS.64.
    const uint2 l0 = *reinterpret_cast<const uint2*>(&spack[h0]);
    const uint2 l1 = *reinterpret_cast<const uint2*>(&spack[h0 + 2]);
    const uint2 l2 = *reinterpret_cast<const uint2*>(&spack[h0 + 4]);
    const unsigned int w0 = l0.x, w1 = l0.y, w2 = l1.x;
    const unsigned int w3 = l1.y, w4 = l2.x, w5 = l2.y;

    const unsigned int r0 = (unsigned)bc0 * LREP;
    const unsigned int r1 = (unsigned)bc1 * LREP;

    // popc(((word ^ rep) + CADD) & MBIT) = # mismatching rows in that column
    #define CNT(wd, rp) __popc((((wd) ^ (rp)) + CADD) & MBIT)
    const int cnt0 = CNT(w0,r0)+CNT(w1,r0)+CNT(w2,r0)+CNT(w3,r0)+CNT(w4,r0);
    const int cnt1 = CNT(w1,r1)+CNT(w2,r1)+CNT(w3,r1)+CNT(w4,r1)+CNT(w5,r1);
    #undef CNT

    float2 o;
    o.x = 1.0f + 1.5f * (float)cnt0;
    o.y = 1.0f + 1.5f * (float)cnt1;

    *reinterpret_cast<float2*>(out + (b * NW + w) * NH + h0) = o;
}

extern "C" void kernel_launch(void* const* d_in, const int* in_sizes, int n_in,
                              void* d_out, int out_size)
{
    const float* x = (const float*)d_in[0];
    const int*   y = (const int*)d_in[1];
    float*       o = (float*)d_out;

    dim3 grid(NW, NB);
    weight_matrix_kernel<<<grid, 256>>>(x, y, o);
}